// round 8
// baseline (speedup 1.0000x reference)
#include <cuda_runtime.h>
#include <cuda_bf16.h>
#include <cstdint>
#include <cstddef>

#define NE 800000
#define NN 50000
#define IN_CH 128
#define HID 64
#define OUT_CH 128
#define NT 6250          // 800000 / 128 edge tiles
#define RS2 0.70710678118654752f

// ---- stage2 smem (bytes), A/B rows pitch 400B (200 bf16) ----
#define A_H 0
#define A_L 51200
#define W_H 102400
#define W_L 153600
#define S_BV 204800
#define SMEM2 205312

// ---- stage1 smem (bytes), pitch 272B (136 bf16) ----
#define S1_A_H 0
#define S1_A_L 34816
#define S1_W_H 69632
#define S1_W_L 87040
#define SMEM1  104448

// Node hidden state (complex interleaved [NN][64] floats), 12.8 MB scratch.
__device__ float g_h[(size_t)NN * HID];

// ---------------------------------------------------------------------------
// Helpers
// ---------------------------------------------------------------------------
__device__ __forceinline__ uint32_t smem_u32(const void* p) {
    uint32_t a;
    asm("{ .reg .u64 t; cvta.to.shared.u64 t, %1; cvt.u32.u64 %0, t; }"
        : "=r"(a) : "l"(p));
    return a;
}

__device__ __forceinline__ int detect_kind(const void* mraw, int* sflags) {
    if (threadIdx.x < 2) sflags[threadIdx.x] = 0;
    __syncthreads();
    int l1 = 0, l23 = 0;
    const unsigned char* m = (const unsigned char*)mraw;
    for (int i = threadIdx.x; i < 2048; i += blockDim.x) {
        unsigned char b = m[i];
        if (b) {
            int r = i & 3;
            if (r == 1) l1 = 1;
            else if (r >= 2) l23 = 1;
        }
    }
    if (l1) atomicOr(&sflags[0], 1);
    if (l23) atomicOr(&sflags[1], 1);
    __syncthreads();
    return sflags[0] ? 0 : (sflags[1] ? 2 : 1);
}
__device__ __forceinline__ bool read_mask(const void* m, int kind, int e) {
    if (kind == 0) return ((const unsigned char*)m)[e] != 0;
    if (kind == 1) return ((const int*)m)[e] != 0;
    return ((const float*)m)[e] != 0.0f;
}

__device__ __forceinline__ void bf16_split(float f, uint16_t& hi, uint16_t& lo) {
    __nv_bfloat16 h = __float2bfloat16(f);
    float r = f - __bfloat162float(h);
    __nv_bfloat16 l = __float2bfloat16(r);
    hi = __bfloat16_as_ushort(h);
    lo = __bfloat16_as_ushort(l);
}

__device__ __forceinline__ void mma16816(float* c, const uint32_t* a,
                                         const uint32_t* b) {
    asm volatile(
        "mma.sync.aligned.m16n8k16.row.col.f32.bf16.bf16.f32 "
        "{%0,%1,%2,%3}, {%4,%5,%6,%7}, {%8,%9}, {%0,%1,%2,%3};"
        : "+f"(c[0]), "+f"(c[1]), "+f"(c[2]), "+f"(c[3])
        : "r"(a[0]), "r"(a[1]), "r"(a[2]), "r"(a[3]), "r"(b[0]), "r"(b[1]));
}

#define LDSM4(r, addr)                                                         \
    asm volatile("ldmatrix.sync.aligned.m8n8.x4.shared.b16 {%0,%1,%2,%3}, [%4];"\
        : "=r"((r)[0]), "=r"((r)[1]), "=r"((r)[2]), "=r"((r)[3]) : "r"(addr))

__device__ __forceinline__ void red_v4(float* p, float a, float b, float c,
                                       float d) {
    asm volatile("red.global.add.v4.f32 [%0], {%1,%2,%3,%4};"
                 :: "l"(p), "f"(a), "f"(b), "f"(c), "f"(d) : "memory");
}

// lane-split metadata: lanes 0-7 load u(row), 8-15 v(row), 16-23 mask(row)
__device__ __forceinline__ int load_lane_meta(const int* __restrict__ ei,
                                              const void* __restrict__ m,
                                              int kind, int eb, int l) {
    if (l < 8) return ei[eb + l];
    if (l < 16) return ei[NE + eb + (l - 8)];
    if (l < 24) {
        int e = eb + (l - 16);
        if (kind == 0) return ((const unsigned char*)m)[e];
        if (kind == 1) return ((const int*)m)[e];
        return (((const float*)m)[e] != 0.0f) ? 1 : 0;
    }
    return 0;
}

// ---------------------------------------------------------------------------
// Stage 1 (mma.sync): z = (EA @ W_in^T), rotate + red.v4 scatter into g_h.
// ---------------------------------------------------------------------------
__global__ void __launch_bounds__(512, 2) stage1_kernel(
    const float* __restrict__ ea, const float* __restrict__ Win,
    const int* __restrict__ ei, const void* __restrict__ mraw)
{
    extern __shared__ __align__(16) char sm1[];
    __shared__ int sflags[2];
    const int tid = threadIdx.x, w = tid >> 5, l = tid & 31;
    const int kind = detect_kind(mraw, sflags);
    const uint32_t sb = smem_u32(sm1);

    for (int x = tid; x < 64 * 64; x += 512) {
        int n = x >> 6, kp = x & 63;
        float2 wv = *(const float2*)(Win + n * IN_CH + 2 * kp);
        uint16_t h0, l0, h1, l1;
        bf16_split(wv.x, h0, l0);
        bf16_split(wv.y, h1, l1);
        uint32_t off = (uint32_t)(n * 272 + 4 * kp);
        *(uint32_t*)(sm1 + S1_W_H + off) = (uint32_t)h0 | ((uint32_t)h1 << 16);
        *(uint32_t*)(sm1 + S1_W_L + off) = (uint32_t)l0 | ((uint32_t)l1 << 16);
    }

    const int wr = w >> 2, wc = w & 3;
    const int rowb = wr * 32, colb = wc * 16;
    const int g = l >> 2, tig = l & 3;
    const uint32_t a_sub = (uint32_t)((rowb + ((l >> 3) & 1) * 8 + (l & 7)) * 272
                                      + (l >> 4) * 16);
    const uint32_t b_sub = (uint32_t)((colb + ((l >> 4) & 1) * 8 + (l & 7)) * 272
                                      + ((l >> 3) & 1) * 16);
    float* zt = (float*)(sm1 + S1_A_H);   // reused as z tile [128][68] fp32

    for (int t = blockIdx.x; t < NT; t += gridDim.x) {
        __syncthreads();   // protect A_H (z of previous tile) until scatter done
        #pragma unroll 2
        for (int rr = 0; rr < 8; rr++) {
            int r = w * 8 + rr, e = t * 128 + r;
            float4 a4 = *(const float4*)(ea + (size_t)e * IN_CH + 4 * l);
            uint16_t h0, lo0, h1, lo1, h2, lo2, h3, lo3;
            bf16_split(a4.x, h0, lo0); bf16_split(a4.y, h1, lo1);
            bf16_split(a4.z, h2, lo2); bf16_split(a4.w, h3, lo3);
            uint2 hv2, lv2;
            hv2.x = (uint32_t)h0 | ((uint32_t)h1 << 16);
            hv2.y = (uint32_t)h2 | ((uint32_t)h3 << 16);
            lv2.x = (uint32_t)lo0 | ((uint32_t)lo1 << 16);
            lv2.y = (uint32_t)lo2 | ((uint32_t)lo3 << 16);
            uint32_t off = (uint32_t)(r * 272 + 8 * l);
            *(uint2*)(sm1 + S1_A_H + off) = hv2;
            *(uint2*)(sm1 + S1_A_L + off) = lv2;
        }
        __syncthreads();

        float acc[2][2][4];
        #pragma unroll
        for (int mf = 0; mf < 2; mf++)
            #pragma unroll
            for (int nf = 0; nf < 2; nf++)
                #pragma unroll
                for (int i = 0; i < 4; i++) acc[mf][nf][i] = 0.f;

        #pragma unroll 1
        for (int pass = 0; pass < 3; pass++) {
            uint32_t Ab = sb + (pass == 1 ? S1_A_L : S1_A_H);
            uint32_t Bb = sb + (pass == 2 ? S1_W_L : S1_W_H);
            uint32_t aa0 = Ab + a_sub, aa1 = aa0 + 16 * 272;
            uint32_t ba = Bb + b_sub;
            #pragma unroll
            for (int ks = 0; ks < 8; ks++) {
                uint32_t A0[4], A1[4], B0[4];
                LDSM4(A0, aa0);
                LDSM4(A1, aa1);
                LDSM4(B0, ba);
                mma16816(acc[0][0], A0, B0);
                mma16816(acc[0][1], A0, B0 + 2);
                mma16816(acc[1][0], A1, B0);
                mma16816(acc[1][1], A1, B0 + 2);
                aa0 += 32; aa1 += 32; ba += 32;
            }
        }
        __syncthreads();   // all warps done reading A tiles -> reuse as z

        #pragma unroll
        for (int mf = 0; mf < 2; mf++) {
            int row = rowb + mf * 16 + g;
            #pragma unroll
            for (int nf = 0; nf < 2; nf++) {
                int n = colb + nf * 8 + 2 * tig;
                *(float2*)(zt + row * 68 + n) =
                    make_float2(acc[mf][nf][0], acc[mf][nf][1]);
                *(float2*)(zt + (row + 8) * 68 + n) =
                    make_float2(acc[mf][nf][2], acc[mf][nf][3]);
            }
        }
        __syncthreads();

        {
            int el = tid >> 2, q = tid & 3;
            int e = t * 128 + el;
            int u = ei[e], v = ei[NE + e];
            bool und = read_mask(mraw, kind, e);
            float cc, ss, dinv;
            if (und) { cc = 1.0f; ss = 0.0f; dinv = (u == v) ? 0.0f : RS2; }
            else     { cc = RS2;  ss = RS2;  dinv = RS2; }
            if (dinv != 0.0f) {
                const float* zr = zt + el * 68 + 16 * q;
                float* hv = g_h + (size_t)v * HID + 16 * q;
                float* hu = g_h + (size_t)u * HID + 16 * q;
                #pragma unroll
                for (int j = 0; j < 4; j++) {
                    float4 z4 = *(const float4*)(zr + 4 * j);
                    float r0 = z4.x * dinv, i0 = z4.y * dinv;
                    float r1 = z4.z * dinv, i1 = z4.w * dinv;
                    red_v4(hv + 4 * j,
                           fmaf(cc, r0, ss * i0), fmaf(cc, i0, -ss * r0),
                           fmaf(cc, r1, ss * i1), fmaf(cc, i1, -ss * r1));
                    red_v4(hu + 4 * j,
                           fmaf(-cc, r0, ss * i0), fmaf(-cc, i0, -ss * r0),
                           fmaf(-cc, r1, ss * i1), fmaf(-cc, i1, -ss * r1));
                }
            }
        }
    }
}

// ---------------------------------------------------------------------------
// Stage 2 (mma.sync, 16 warps, fused 3-pass hi/lo): per 128-edge tile
//   A = [Y | EA] (128 x 192), B = [W_out | W_skip] (128 x 192)
//   D = A @ B^T = AhBh + AlBh + AhBl; out = D + (b_skip + bias)
// Fused k-loop: load A_H/A_L/B_H/B_L fragments once per k-step (8 LDSM),
// issue all 24 MMAs -> 96 LDSM/warp/tile vs 144 for separate passes.
// Indices prefetched one tile ahead (1 reg); g_h gathers batched at Phase A
// start (L2-resident after stage1 -> one ~260cyc exposure per warp).
// ---------------------------------------------------------------------------
__global__ void __launch_bounds__(512, 1) stage2_kernel(
    const float* __restrict__ ea, const float* __restrict__ Wout,
    const float* __restrict__ Wskip, const float* __restrict__ bskip,
    const float* __restrict__ bias, const int* __restrict__ ei,
    const void* __restrict__ mraw, float* __restrict__ out)
{
    extern __shared__ __align__(16) char sm[];
    __shared__ int sflags[2];
    const int tid = threadIdx.x, w = tid >> 5, l = tid & 31;
    const int kind = detect_kind(mraw, sflags);
    const uint32_t sb = smem_u32(sm);
    float* bv = (float*)(sm + S_BV);

    for (int x = tid; x < 128 * 32; x += 512) {         // W_out: k 0..63
        int n = x >> 5, kp = x & 31;
        float2 wv = *(const float2*)(Wout + n * HID + 2 * kp);
        uint16_t h0, l0, h1, l1;
        bf16_split(wv.x, h0, l0);
        bf16_split(wv.y, h1, l1);
        uint32_t off = (uint32_t)(n * 400 + 4 * kp);
        *(uint32_t*)(sm + W_H + off) = (uint32_t)h0 | ((uint32_t)h1 << 16);
        *(uint32_t*)(sm + W_L + off) = (uint32_t)l0 | ((uint32_t)l1 << 16);
    }
    for (int x = tid; x < 128 * 64; x += 512) {         // W_skip: k 64..191
        int n = x >> 6, kp = x & 63;
        float2 wv = *(const float2*)(Wskip + n * IN_CH + 2 * kp);
        uint16_t h0, l0, h1, l1;
        bf16_split(wv.x, h0, l0);
        bf16_split(wv.y, h1, l1);
        uint32_t off = (uint32_t)(n * 400 + 128 + 4 * kp);
        *(uint32_t*)(sm + W_H + off) = (uint32_t)h0 | ((uint32_t)h1 << 16);
        *(uint32_t*)(sm + W_L + off) = (uint32_t)l0 | ((uint32_t)l1 << 16);
    }
    if (tid < 128) bv[tid] = bskip[tid] + bias[tid];
    __syncthreads();

    const int wr = w >> 2, wc = w & 3;
    const int rowb = wr * 32, colb = wc * 32;
    const int g = l >> 2, tig = l & 3;
    const uint32_t a_sub = (uint32_t)((rowb + ((l >> 3) & 1) * 8 + (l & 7)) * 400
                                      + (l >> 4) * 16);
    const uint32_t b_sub = (uint32_t)((colb + ((l >> 4) & 1) * 8 + (l & 7)) * 400
                                      + ((l >> 3) & 1) * 16);

    // Prologue: prefetch first tile's indices (1 register)
    const int t0 = blockIdx.x;
    int pre = 0;
    if (t0 < NT)
        pre = load_lane_meta(ei, mraw, kind, t0 * 128 + w * 8, l);

    for (int t = t0; t < NT; t += gridDim.x) {
        // ---- Phase A: batched L2-hit gathers, stream EA, build tiles ----
        float2 phv[8], phu[8];
        #pragma unroll
        for (int r = 0; r < 8; r++) {
            int u = __shfl_sync(0xffffffffu, pre, r);
            int v = __shfl_sync(0xffffffffu, pre, r + 8);
            phv[r] = *(const float2*)(g_h + (size_t)v * HID + 2 * l);
            phu[r] = *(const float2*)(g_h + (size_t)u * HID + 2 * l);
        }
        #pragma unroll
        for (int b = 0; b < 2; b++) {
            float4 a4[4];
            #pragma unroll
            for (int rr = 0; rr < 4; rr++) {
                int e = t * 128 + w * 8 + b * 4 + rr;
                a4[rr] = *(const float4*)(ea + (size_t)e * IN_CH + 4 * l);
            }
            #pragma unroll
            for (int rr = 0; rr < 4; rr++) {
                int r = w * 8 + b * 4 + rr;
                uint16_t h0, lo0, h1, lo1, h2, lo2, h3, lo3;
                bf16_split(a4[rr].x, h0, lo0); bf16_split(a4[rr].y, h1, lo1);
                bf16_split(a4[rr].z, h2, lo2); bf16_split(a4[rr].w, h3, lo3);
                uint2 hv2, lv2;
                hv2.x = (uint32_t)h0 | ((uint32_t)h1 << 16);
                hv2.y = (uint32_t)h2 | ((uint32_t)h3 << 16);
                lv2.x = (uint32_t)lo0 | ((uint32_t)lo1 << 16);
                lv2.y = (uint32_t)lo2 | ((uint32_t)lo3 << 16);
                uint32_t off = (uint32_t)(r * 400 + 128 + 8 * l);
                *(uint2*)(sm + A_H + off) = hv2;
                *(uint2*)(sm + A_L + off) = lv2;

                int rq = b * 4 + rr;
                int u = __shfl_sync(0xffffffffu, pre, rq);
                int v = __shfl_sync(0xffffffffu, pre, rq + 8);
                int mm = __shfl_sync(0xffffffffu, pre, rq + 16);
                float cc, ss, dinv;
                if (mm) { cc = 1.0f; ss = 0.0f; dinv = (u == v) ? 0.0f : RS2; }
                else    { cc = RS2;  ss = RS2;  dinv = RS2; }
                float av = fmaxf(phv[rq].x, 0.f), bvv = fmaxf(phv[rq].y, 0.f);
                float au = fmaxf(phu[rq].x, 0.f), bu  = fmaxf(phu[rq].y, 0.f);
                float yr = dinv * (cc * (av - au) - ss * (bvv + bu));
                float yi = dinv * (cc * (bvv - bu) + ss * (av + au));
                uint16_t yh0, yl0, yh1, yl1;
                bf16_split(yr, yh0, yl0);
                bf16_split(yi, yh1, yl1);
                uint32_t off2 = (uint32_t)(r * 400 + 4 * l);
                *(uint32_t*)(sm + A_H + off2) = (uint32_t)yh0 | ((uint32_t)yh1 << 16);
                *(uint32_t*)(sm + A_L + off2) = (uint32_t)yl0 | ((uint32_t)yl1 << 16);
            }
        }
        // prefetch next tile's indices (land during Phase B)
        const int tn = t + gridDim.x;
        int pre_n = 0;
        if (tn < NT)
            pre_n = load_lane_meta(ei, mraw, kind, tn * 128 + w * 8, l);
        pre = pre_n;
        __syncthreads();

        // ---- Phase B: fused 3-pass hi/lo mma over K=192 ----
        float acc[2][4][4];
        #pragma unroll
        for (int mf = 0; mf < 2; mf++)
            #pragma unroll
            for (int nf = 0; nf < 4; nf++)
                #pragma unroll
                for (int i = 0; i < 4; i++) acc[mf][nf][i] = 0.f;

        {
            uint32_t aH0 = sb + A_H + a_sub, aH1 = aH0 + 16 * 400;
            uint32_t aL0 = sb + A_L + a_sub, aL1 = aL0 + 16 * 400;
            uint32_t bH0 = sb + W_H + b_sub, bH1 = bH0 + 16 * 400;
            uint32_t bL0 = sb + W_L + b_sub, bL1 = bL0 + 16 * 400;
            #pragma unroll 2
            for (int ks = 0; ks < 12; ks++) {
                uint32_t AH0[4], AH1[4], AL0[4], AL1[4];
                uint32_t BH0[4], BH1[4], BL0[4], BL1[4];
                LDSM4(AH0, aH0);
                LDSM4(AH1, aH1);
                LDSM4(BH0, bH0);
                LDSM4(BH1, bH1);
                LDSM4(AL0, aL0);
                LDSM4(AL1, aL1);
                LDSM4(BL0, bL0);
                LDSM4(BL1, bL1);
                // Ah x Bh
                mma16816(acc[0][0], AH0, BH0);
                mma16816(acc[0][1], AH0, BH0 + 2);
                mma16816(acc[0][2], AH0, BH1);
                mma16816(acc[0][3], AH0, BH1 + 2);
                mma16816(acc[1][0], AH1, BH0);
                mma16816(acc[1][1], AH1, BH0 + 2);
                mma16816(acc[1][2], AH1, BH1);
                mma16816(acc[1][3], AH1, BH1 + 2);
                // Al x Bh
                mma16816(acc[0][0], AL0, BH0);
                mma16816(acc[0][1], AL0, BH0 + 2);
                mma16816(acc[0][2], AL0, BH1);
                mma16816(acc[0][3], AL0, BH1 + 2);
                mma16816(acc[1][0], AL1, BH0);
                mma16816(acc[1][1], AL1, BH0 + 2);
                mma16816(acc[1][2], AL1, BH1);
                mma16816(acc[1][3], AL1, BH1 + 2);
                // Ah x Bl
                mma16816(acc[0][0], AH0, BL0);
                mma16816(acc[0][1], AH0, BL0 + 2);
                mma16816(acc[0][2], AH0, BL1);
                mma16816(acc[0][3], AH0, BL1 + 2);
                mma16816(acc[1][0], AH1, BL0);
                mma16816(acc[1][1], AH1, BL0 + 2);
                mma16816(acc[1][2], AH1, BL1);
                mma16816(acc[1][3], AH1, BL1 + 2);
                aH0 += 32; aH1 += 32; aL0 += 32; aL1 += 32;
                bH0 += 32; bH1 += 32; bL0 += 32; bL1 += 32;
            }
        }

        // ---- Phase C: bias + coalesced stores ----
        #pragma unroll
        for (int mf = 0; mf < 2; mf++) {
            int e0 = t * 128 + rowb + mf * 16 + g;
            #pragma unroll
            for (int nf = 0; nf < 4; nf++) {
                int c = colb + nf * 8 + 2 * tig;
                float2 bb = *(const float2*)(bv + c);
                float2 v0, v1;
                v0.x = acc[mf][nf][0] + bb.x;
                v0.y = acc[mf][nf][1] + bb.y;
                v1.x = acc[mf][nf][2] + bb.x;
                v1.y = acc[mf][nf][3] + bb.y;
                *(float2*)(out + (size_t)e0 * OUT_CH + c) = v0;
                *(float2*)(out + (size_t)(e0 + 8) * OUT_CH + c) = v1;
            }
        }
        __syncthreads();
    }
}

extern "C" void kernel_launch(void* const* d_in, const int* in_sizes, int n_in,
                              void* d_out, int out_size) {
    (void)in_sizes; (void)n_in; (void)out_size;
    const int*   ei    = (const int*)d_in[0];
    const void*  mask  = d_in[1];
    const float* ea    = (const float*)d_in[2];
    const float* Win   = (const float*)d_in[3];
    const float* Wout  = (const float*)d_in[4];
    const float* Wskip = (const float*)d_in[5];
    const float* bskip = (const float*)d_in[6];
    const float* bias  = (const float*)d_in[7];
    float* out = (float*)d_out;

    int dev = 0;
    cudaGetDevice(&dev);
    int sms = 148;
    cudaDeviceGetAttribute(&sms, cudaDevAttrMultiProcessorCount, dev);

    void* hptr = nullptr;
    cudaGetSymbolAddress(&hptr, g_h);

    cudaFuncSetAttribute(stage1_kernel,
                         cudaFuncAttributeMaxDynamicSharedMemorySize, SMEM1);
    cudaFuncSetAttribute(stage2_kernel,
                         cudaFuncAttributeMaxDynamicSharedMemorySize, SMEM2);

    cudaMemsetAsync(hptr, 0, sizeof(float) * (size_t)NN * HID);
    stage1_kernel<<<sms * 2, 512, SMEM1>>>(ea, Win, ei, mask);
    stage2_kernel<<<sms, 512, SMEM2>>>(ea, Wout, Wskip, bskip, bias, ei, mask, out);
}

// round 9
// speedup vs baseline: 1.0928x; 1.0928x over previous
#include <cuda_runtime.h>
#include <cuda_bf16.h>
#include <cstdint>
#include <cstddef>

#define NE 800000
#define NN 50000
#define IN_CH 128
#define HID 64
#define OUT_CH 128
#define NT 6250          // 128-edge tiles (stage1)
#define NT2 12500        // 64-edge tiles (stage2)
#define RS2 0.70710678118654752f

// ---- stage2 smem (bytes): per-group A buffers (64 rows x 400B, hi+lo),
//      shared W tiles (128 rows x 400B, hi+lo), bias ----
#define A_GRP 51200      // per-group A region (hi 25600 + lo 25600)
#define A_LOFF 25600
#define W_H 102400
#define W_L 153600
#define S_BV 204800
#define SMEM2 205312

// ---- stage1 smem (bytes), pitch 272B (136 bf16) ----
#define S1_A_H 0
#define S1_A_L 34816
#define S1_W_H 69632
#define S1_W_L 87040
#define SMEM1  104448

// Node hidden state (complex interleaved [NN][64] floats), 12.8 MB scratch.
__device__ float g_h[(size_t)NN * HID];

// ---------------------------------------------------------------------------
// Helpers
// ---------------------------------------------------------------------------
__device__ __forceinline__ uint32_t smem_u32(const void* p) {
    uint32_t a;
    asm("{ .reg .u64 t; cvta.to.shared.u64 t, %1; cvt.u32.u64 %0, t; }"
        : "=r"(a) : "l"(p));
    return a;
}

__device__ __forceinline__ int detect_kind(const void* mraw, int* sflags) {
    if (threadIdx.x < 2) sflags[threadIdx.x] = 0;
    __syncthreads();
    int l1 = 0, l23 = 0;
    const unsigned char* m = (const unsigned char*)mraw;
    for (int i = threadIdx.x; i < 2048; i += blockDim.x) {
        unsigned char b = m[i];
        if (b) {
            int r = i & 3;
            if (r == 1) l1 = 1;
            else if (r >= 2) l23 = 1;
        }
    }
    if (l1) atomicOr(&sflags[0], 1);
    if (l23) atomicOr(&sflags[1], 1);
    __syncthreads();
    return sflags[0] ? 0 : (sflags[1] ? 2 : 1);
}
__device__ __forceinline__ bool read_mask(const void* m, int kind, int e) {
    if (kind == 0) return ((const unsigned char*)m)[e] != 0;
    if (kind == 1) return ((const int*)m)[e] != 0;
    return ((const float*)m)[e] != 0.0f;
}

__device__ __forceinline__ void bf16_split(float f, uint16_t& hi, uint16_t& lo) {
    __nv_bfloat16 h = __float2bfloat16(f);
    float r = f - __bfloat162float(h);
    __nv_bfloat16 l = __float2bfloat16(r);
    hi = __bfloat16_as_ushort(h);
    lo = __bfloat16_as_ushort(l);
}

__device__ __forceinline__ void mma16816(float* c, const uint32_t* a,
                                         const uint32_t* b) {
    asm volatile(
        "mma.sync.aligned.m16n8k16.row.col.f32.bf16.bf16.f32 "
        "{%0,%1,%2,%3}, {%4,%5,%6,%7}, {%8,%9}, {%0,%1,%2,%3};"
        : "+f"(c[0]), "+f"(c[1]), "+f"(c[2]), "+f"(c[3])
        : "r"(a[0]), "r"(a[1]), "r"(a[2]), "r"(a[3]), "r"(b[0]), "r"(b[1]));
}

#define LDSM4(r, addr)                                                         \
    asm volatile("ldmatrix.sync.aligned.m8n8.x4.shared.b16 {%0,%1,%2,%3}, [%4];"\
        : "=r"((r)[0]), "=r"((r)[1]), "=r"((r)[2]), "=r"((r)[3]) : "r"(addr))

__device__ __forceinline__ void red_v4(float* p, float a, float b, float c,
                                       float d) {
    asm volatile("red.global.add.v4.f32 [%0], {%1,%2,%3,%4};"
                 :: "l"(p), "f"(a), "f"(b), "f"(c), "f"(d) : "memory");
}

__device__ __forceinline__ void bar_grp(int id) {
    asm volatile("bar.sync %0, 256;" :: "r"(id) : "memory");
}

// lane-split metadata: lanes 0-7 load u(row), 8-15 v(row), 16-23 mask(row)
__device__ __forceinline__ int load_lane_meta(const int* __restrict__ ei,
                                              const void* __restrict__ m,
                                              int kind, int eb, int l) {
    if (l < 8) return ei[eb + l];
    if (l < 16) return ei[NE + eb + (l - 8)];
    if (l < 24) {
        int e = eb + (l - 16);
        if (kind == 0) return ((const unsigned char*)m)[e];
        if (kind == 1) return ((const int*)m)[e];
        return (((const float*)m)[e] != 0.0f) ? 1 : 0;
    }
    return 0;
}

// ---------------------------------------------------------------------------
// Stage 1 (mma.sync): z = (EA @ W_in^T), rotate + red.v4 scatter into g_h.
// ---------------------------------------------------------------------------
__global__ void __launch_bounds__(512, 2) stage1_kernel(
    const float* __restrict__ ea, const float* __restrict__ Win,
    const int* __restrict__ ei, const void* __restrict__ mraw)
{
    extern __shared__ __align__(16) char sm1[];
    __shared__ int sflags[2];
    const int tid = threadIdx.x, w = tid >> 5, l = tid & 31;
    const int kind = detect_kind(mraw, sflags);
    const uint32_t sb = smem_u32(sm1);

    for (int x = tid; x < 64 * 64; x += 512) {
        int n = x >> 6, kp = x & 63;
        float2 wv = *(const float2*)(Win + n * IN_CH + 2 * kp);
        uint16_t h0, l0, h1, l1;
        bf16_split(wv.x, h0, l0);
        bf16_split(wv.y, h1, l1);
        uint32_t off = (uint32_t)(n * 272 + 4 * kp);
        *(uint32_t*)(sm1 + S1_W_H + off) = (uint32_t)h0 | ((uint32_t)h1 << 16);
        *(uint32_t*)(sm1 + S1_W_L + off) = (uint32_t)l0 | ((uint32_t)l1 << 16);
    }

    const int wr = w >> 2, wc = w & 3;
    const int rowb = wr * 32, colb = wc * 16;
    const int g = l >> 2, tig = l & 3;
    const uint32_t a_sub = (uint32_t)((rowb + ((l >> 3) & 1) * 8 + (l & 7)) * 272
                                      + (l >> 4) * 16);
    const uint32_t b_sub = (uint32_t)((colb + ((l >> 4) & 1) * 8 + (l & 7)) * 272
                                      + ((l >> 3) & 1) * 16);
    float* zt = (float*)(sm1 + S1_A_H);   // reused as z tile [128][68] fp32

    for (int t = blockIdx.x; t < NT; t += gridDim.x) {
        __syncthreads();   // protect A_H (z of previous tile) until scatter done
        #pragma unroll 2
        for (int rr = 0; rr < 8; rr++) {
            int r = w * 8 + rr, e = t * 128 + r;
            float4 a4 = *(const float4*)(ea + (size_t)e * IN_CH + 4 * l);
            uint16_t h0, lo0, h1, lo1, h2, lo2, h3, lo3;
            bf16_split(a4.x, h0, lo0); bf16_split(a4.y, h1, lo1);
            bf16_split(a4.z, h2, lo2); bf16_split(a4.w, h3, lo3);
            uint2 hv2, lv2;
            hv2.x = (uint32_t)h0 | ((uint32_t)h1 << 16);
            hv2.y = (uint32_t)h2 | ((uint32_t)h3 << 16);
            lv2.x = (uint32_t)lo0 | ((uint32_t)lo1 << 16);
            lv2.y = (uint32_t)lo2 | ((uint32_t)lo3 << 16);
            uint32_t off = (uint32_t)(r * 272 + 8 * l);
            *(uint2*)(sm1 + S1_A_H + off) = hv2;
            *(uint2*)(sm1 + S1_A_L + off) = lv2;
        }
        __syncthreads();

        float acc[2][2][4];
        #pragma unroll
        for (int mf = 0; mf < 2; mf++)
            #pragma unroll
            for (int nf = 0; nf < 2; nf++)
                #pragma unroll
                for (int i = 0; i < 4; i++) acc[mf][nf][i] = 0.f;

        #pragma unroll 1
        for (int pass = 0; pass < 3; pass++) {
            uint32_t Ab = sb + (pass == 1 ? S1_A_L : S1_A_H);
            uint32_t Bb = sb + (pass == 2 ? S1_W_L : S1_W_H);
            uint32_t aa0 = Ab + a_sub, aa1 = aa0 + 16 * 272;
            uint32_t ba = Bb + b_sub;
            #pragma unroll
            for (int ks = 0; ks < 8; ks++) {
                uint32_t A0[4], A1[4], B0[4];
                LDSM4(A0, aa0);
                LDSM4(A1, aa1);
                LDSM4(B0, ba);
                mma16816(acc[0][0], A0, B0);
                mma16816(acc[0][1], A0, B0 + 2);
                mma16816(acc[1][0], A1, B0);
                mma16816(acc[1][1], A1, B0 + 2);
                aa0 += 32; aa1 += 32; ba += 32;
            }
        }
        __syncthreads();   // all warps done reading A tiles -> reuse as z

        #pragma unroll
        for (int mf = 0; mf < 2; mf++) {
            int row = rowb + mf * 16 + g;
            #pragma unroll
            for (int nf = 0; nf < 2; nf++) {
                int n = colb + nf * 8 + 2 * tig;
                *(float2*)(zt + row * 68 + n) =
                    make_float2(acc[mf][nf][0], acc[mf][nf][1]);
                *(float2*)(zt + (row + 8) * 68 + n) =
                    make_float2(acc[mf][nf][2], acc[mf][nf][3]);
            }
        }
        __syncthreads();

        {
            int el = tid >> 2, q = tid & 3;
            int e = t * 128 + el;
            int u = ei[e], v = ei[NE + e];
            bool und = read_mask(mraw, kind, e);
            float cc, ss, dinv;
            if (und) { cc = 1.0f; ss = 0.0f; dinv = (u == v) ? 0.0f : RS2; }
            else     { cc = RS2;  ss = RS2;  dinv = RS2; }
            if (dinv != 0.0f) {
                const float* zr = zt + el * 68 + 16 * q;
                float* hv = g_h + (size_t)v * HID + 16 * q;
                float* hu = g_h + (size_t)u * HID + 16 * q;
                #pragma unroll
                for (int j = 0; j < 4; j++) {
                    float4 z4 = *(const float4*)(zr + 4 * j);
                    float r0 = z4.x * dinv, i0 = z4.y * dinv;
                    float r1 = z4.z * dinv, i1 = z4.w * dinv;
                    red_v4(hv + 4 * j,
                           fmaf(cc, r0, ss * i0), fmaf(cc, i0, -ss * r0),
                           fmaf(cc, r1, ss * i1), fmaf(cc, i1, -ss * r1));
                    red_v4(hu + 4 * j,
                           fmaf(-cc, r0, ss * i0), fmaf(-cc, i0, -ss * r0),
                           fmaf(-cc, r1, ss * i1), fmaf(-cc, i1, -ss * r1));
                }
            }
        }
    }
}

// ---------------------------------------------------------------------------
// Stage 2: two-tile ping-pong. 16 warps split into two groups of 8; each
// group owns a private 64-edge tile (A hi/lo buffers) + named barrier and
// alternates Phase A/C with the other group's MMA phase, keeping the tensor
// pipe fed. W tiles shared read-only. Fused 3-pass hi/lo per k-step.
// ---------------------------------------------------------------------------
__global__ void __launch_bounds__(512, 1) stage2_kernel(
    const float* __restrict__ ea, const float* __restrict__ Wout,
    const float* __restrict__ Wskip, const float* __restrict__ bskip,
    const float* __restrict__ bias, const int* __restrict__ ei,
    const void* __restrict__ mraw, float* __restrict__ out)
{
    extern __shared__ __align__(16) char sm[];
    __shared__ int sflags[2];
    const int tid = threadIdx.x, l = tid & 31;
    const int kind = detect_kind(mraw, sflags);
    const uint32_t sb = smem_u32(sm);
    float* bv = (float*)(sm + S_BV);

    for (int x = tid; x < 128 * 32; x += 512) {         // W_out: k 0..63
        int n = x >> 5, kp = x & 31;
        float2 wv = *(const float2*)(Wout + n * HID + 2 * kp);
        uint16_t h0, l0, h1, l1;
        bf16_split(wv.x, h0, l0);
        bf16_split(wv.y, h1, l1);
        uint32_t off = (uint32_t)(n * 400 + 4 * kp);
        *(uint32_t*)(sm + W_H + off) = (uint32_t)h0 | ((uint32_t)h1 << 16);
        *(uint32_t*)(sm + W_L + off) = (uint32_t)l0 | ((uint32_t)l1 << 16);
    }
    for (int x = tid; x < 128 * 64; x += 512) {         // W_skip: k 64..191
        int n = x >> 6, kp = x & 63;
        float2 wv = *(const float2*)(Wskip + n * IN_CH + 2 * kp);
        uint16_t h0, l0, h1, l1;
        bf16_split(wv.x, h0, l0);
        bf16_split(wv.y, h1, l1);
        uint32_t off = (uint32_t)(n * 400 + 128 + 4 * kp);
        *(uint32_t*)(sm + W_H + off) = (uint32_t)h0 | ((uint32_t)h1 << 16);
        *(uint32_t*)(sm + W_L + off) = (uint32_t)l0 | ((uint32_t)l1 << 16);
    }
    if (tid < 128) bv[tid] = bskip[tid] + bias[tid];
    __syncthreads();

    const int grp = tid >> 8;            // 0 or 1
    const int w8 = (tid >> 5) & 7;       // warp index within group
    const int barid = grp + 1;
    const uint32_t aBase = sb + (uint32_t)grp * A_GRP;

    const int wr = w8 >> 2, wc = w8 & 3; // 2x4 warp grid over 64x128 output
    const int rowb = wr * 32, colb = wc * 32;
    const int g = l >> 2, tig = l & 3;
    const uint32_t a_sub = (uint32_t)((rowb + ((l >> 3) & 1) * 8 + (l & 7)) * 400
                                      + (l >> 4) * 16);
    const uint32_t b_sub = (uint32_t)((colb + ((l >> 4) & 1) * 8 + (l & 7)) * 400
                                      + ((l >> 3) & 1) * 16);

    const int t0 = blockIdx.x * 2 + grp;
    const int tstride = gridDim.x * 2;
    int pre = 0;
    if (t0 < NT2)
        pre = load_lane_meta(ei, mraw, kind, t0 * 64 + w8 * 8, l);

    for (int t = t0; t < NT2; t += tstride) {
        // ---- Phase A: batched L2-hit gathers, stream EA, build tiles ----
        float2 phv[8], phu[8];
        #pragma unroll
        for (int r = 0; r < 8; r++) {
            int u = __shfl_sync(0xffffffffu, pre, r);
            int v = __shfl_sync(0xffffffffu, pre, r + 8);
            phv[r] = *(const float2*)(g_h + (size_t)v * HID + 2 * l);
            phu[r] = *(const float2*)(g_h + (size_t)u * HID + 2 * l);
        }
        #pragma unroll
        for (int b = 0; b < 2; b++) {
            float4 a4[4];
            #pragma unroll
            for (int rr = 0; rr < 4; rr++) {
                int e = t * 64 + w8 * 8 + b * 4 + rr;
                a4[rr] = *(const float4*)(ea + (size_t)e * IN_CH + 4 * l);
            }
            #pragma unroll
            for (int rr = 0; rr < 4; rr++) {
                int r = w8 * 8 + b * 4 + rr;
                uint16_t h0, lo0, h1, lo1, h2, lo2, h3, lo3;
                bf16_split(a4[rr].x, h0, lo0); bf16_split(a4[rr].y, h1, lo1);
                bf16_split(a4[rr].z, h2, lo2); bf16_split(a4[rr].w, h3, lo3);
                uint2 hv2, lv2;
                hv2.x = (uint32_t)h0 | ((uint32_t)h1 << 16);
                hv2.y = (uint32_t)h2 | ((uint32_t)h3 << 16);
                lv2.x = (uint32_t)lo0 | ((uint32_t)lo1 << 16);
                lv2.y = (uint32_t)lo2 | ((uint32_t)lo3 << 16);
                uint32_t off = (uint32_t)(r * 400 + 128 + 8 * l);
                *(uint2*)(sm + (aBase - sb) + off) = hv2;
                *(uint2*)(sm + (aBase - sb) + A_LOFF + off) = lv2;

                int rq = b * 4 + rr;
                int u = __shfl_sync(0xffffffffu, pre, rq);
                int v = __shfl_sync(0xffffffffu, pre, rq + 8);
                int mm = __shfl_sync(0xffffffffu, pre, rq + 16);
                float cc, ss, dinv;
                if (mm) { cc = 1.0f; ss = 0.0f; dinv = (u == v) ? 0.0f : RS2; }
                else    { cc = RS2;  ss = RS2;  dinv = RS2; }
                float av = fmaxf(phv[rq].x, 0.f), bvv = fmaxf(phv[rq].y, 0.f);
                float au = fmaxf(phu[rq].x, 0.f), bu  = fmaxf(phu[rq].y, 0.f);
                float yr = dinv * (cc * (av - au) - ss * (bvv + bu));
                float yi = dinv * (cc * (bvv - bu) + ss * (av + au));
                uint16_t yh0, yl0, yh1, yl1;
                bf16_split(yr, yh0, yl0);
                bf16_split(yi, yh1, yl1);
                uint32_t off2 = (uint32_t)(r * 400 + 4 * l);
                *(uint32_t*)(sm + (aBase - sb) + off2) =
                    (uint32_t)yh0 | ((uint32_t)yh1 << 16);
                *(uint32_t*)(sm + (aBase - sb) + A_LOFF + off2) =
                    (uint32_t)yl0 | ((uint32_t)yl1 << 16);
            }
        }
        // prefetch next tile's indices (land during Phase B)
        const int tn = t + tstride;
        pre = (tn < NT2) ? load_lane_meta(ei, mraw, kind, tn * 64 + w8 * 8, l) : 0;
        bar_grp(barid);

        // ---- Phase B: fused 3-pass hi/lo mma over K=192 ----
        float acc[2][4][4];
        #pragma unroll
        for (int mf = 0; mf < 2; mf++)
            #pragma unroll
            for (int nf = 0; nf < 4; nf++)
                #pragma unroll
                for (int i = 0; i < 4; i++) acc[mf][nf][i] = 0.f;

        {
            uint32_t aH0 = aBase + a_sub, aH1 = aH0 + 16 * 400;
            uint32_t aL0 = aBase + A_LOFF + a_sub, aL1 = aL0 + 16 * 400;
            uint32_t bH0 = sb + W_H + b_sub, bH1 = bH0 + 16 * 400;
            uint32_t bL0 = sb + W_L + b_sub, bL1 = bL0 + 16 * 400;
            #pragma unroll 2
            for (int ks = 0; ks < 12; ks++) {
                uint32_t AH0[4], AH1[4], AL0[4], AL1[4];
                uint32_t BH0[4], BH1[4], BL0[4], BL1[4];
                LDSM4(AH0, aH0);
                LDSM4(AH1, aH1);
                LDSM4(BH0, bH0);
                LDSM4(BH1, bH1);
                LDSM4(AL0, aL0);
                LDSM4(AL1, aL1);
                LDSM4(BL0, bL0);
                LDSM4(BL1, bL1);
                mma16816(acc[0][0], AH0, BH0);
                mma16816(acc[0][1], AH0, BH0 + 2);
                mma16816(acc[0][2], AH0, BH1);
                mma16816(acc[0][3], AH0, BH1 + 2);
                mma16816(acc[1][0], AH1, BH0);
                mma16816(acc[1][1], AH1, BH0 + 2);
                mma16816(acc[1][2], AH1, BH1);
                mma16816(acc[1][3], AH1, BH1 + 2);
                mma16816(acc[0][0], AL0, BH0);
                mma16816(acc[0][1], AL0, BH0 + 2);
                mma16816(acc[0][2], AL0, BH1);
                mma16816(acc[0][3], AL0, BH1 + 2);
                mma16816(acc[1][0], AL1, BH0);
                mma16816(acc[1][1], AL1, BH0 + 2);
                mma16816(acc[1][2], AL1, BH1);
                mma16816(acc[1][3], AL1, BH1 + 2);
                mma16816(acc[0][0], AH0, BL0);
                mma16816(acc[0][1], AH0, BL0 + 2);
                mma16816(acc[0][2], AH0, BL1);
                mma16816(acc[0][3], AH0, BL1 + 2);
                mma16816(acc[1][0], AH1, BL0);
                mma16816(acc[1][1], AH1, BL0 + 2);
                mma16816(acc[1][2], AH1, BL1);
                mma16816(acc[1][3], AH1, BL1 + 2);
                aH0 += 32; aH1 += 32; aL0 += 32; aL1 += 32;
                bH0 += 32; bH1 += 32; bL0 += 32; bL1 += 32;
            }
        }

        // ---- Phase C: bias + coalesced stores ----
        #pragma unroll
        for (int mf = 0; mf < 2; mf++) {
            int e0 = t * 64 + rowb + mf * 16 + g;
            #pragma unroll
            for (int nf = 0; nf < 4; nf++) {
                int c = colb + nf * 8 + 2 * tig;
                float2 bb = *(const float2*)(bv + c);
                float2 v0, v1;
                v0.x = acc[mf][nf][0] + bb.x;
                v0.y = acc[mf][nf][1] + bb.y;
                v1.x = acc[mf][nf][2] + bb.x;
                v1.y = acc[mf][nf][3] + bb.y;
                *(float2*)(out + (size_t)e0 * OUT_CH + c) = v0;
                *(float2*)(out + (size_t)(e0 + 8) * OUT_CH + c) = v1;
            }
        }
        bar_grp(barid);   // A buffers free for next Phase A
    }
}

extern "C" void kernel_launch(void* const* d_in, const int* in_sizes, int n_in,
                              void* d_out, int out_size) {
    (void)in_sizes; (void)n_in; (void)out_size;
    const int*   ei    = (const int*)d_in[0];
    const void*  mask  = d_in[1];
    const float* ea    = (const float*)d_in[2];
    const float* Win   = (const float*)d_in[3];
    const float* Wout  = (const float*)d_in[4];
    const float* Wskip = (const float*)d_in[5];
    const float* bskip = (const float*)d_in[6];
    const float* bias  = (const float*)d_in[7];
    float* out = (float*)d_out;

    int dev = 0;
    cudaGetDevice(&dev);
    int sms = 148;
    cudaDeviceGetAttribute(&sms, cudaDevAttrMultiProcessorCount, dev);

    void* hptr = nullptr;
    cudaGetSymbolAddress(&hptr, g_h);

    cudaFuncSetAttribute(stage1_kernel,
                         cudaFuncAttributeMaxDynamicSharedMemorySize, SMEM1);
    cudaFuncSetAttribute(stage2_kernel,
                         cudaFuncAttributeMaxDynamicSharedMemorySize, SMEM2);

    cudaMemsetAsync(hptr, 0, sizeof(float) * (size_t)NN * HID);
    stage1_kernel<<<sms * 2, 512, SMEM1>>>(ea, Win, ei, mask);
    stage2_kernel<<<sms, 512, SMEM2>>>(ea, Wout, Wskip, bskip, bias, ei, mask, out);
}

// round 10
// speedup vs baseline: 1.1112x; 1.0168x over previous
#include <cuda_runtime.h>
#include <cuda_bf16.h>
#include <cstdint>
#include <cstddef>

#define NE 800000
#define NN 50000
#define IN_CH 128
#define HID 64
#define OUT_CH 128
#define NT 6250          // 128-edge tiles (stage1)
#define NT2 12500        // 64-edge tiles (stage2)
#define RS2 0.70710678118654752f

// ---- stage2 smem (bytes): per-group A buffers (64 rows x 400B, hi+lo),
//      shared W tiles (128 rows x 400B, hi+lo), bias ----
#define A_GRP 51200      // per-group A region (hi 25600 + lo 25600)
#define A_LOFF 25600
#define W_H 102400
#define W_L 153600
#define S_BV 204800
#define SMEM2 205312

// ---- stage1 smem (bytes), pitch 272B (136 bf16) ----
#define S1_A_H 0
#define S1_A_L 34816
#define S1_W_H 69632
#define S1_W_L 87040
#define SMEM1  104448

// Node hidden state (complex interleaved [NN][64] floats), 12.8 MB scratch.
__device__ float g_h[(size_t)NN * HID];

// ---------------------------------------------------------------------------
// Helpers
// ---------------------------------------------------------------------------
__device__ __forceinline__ uint32_t smem_u32(const void* p) {
    uint32_t a;
    asm("{ .reg .u64 t; cvta.to.shared.u64 t, %1; cvt.u32.u64 %0, t; }"
        : "=r"(a) : "l"(p));
    return a;
}

__device__ __forceinline__ int detect_kind(const void* mraw, int* sflags) {
    if (threadIdx.x < 2) sflags[threadIdx.x] = 0;
    __syncthreads();
    int l1 = 0, l23 = 0;
    const unsigned char* m = (const unsigned char*)mraw;
    for (int i = threadIdx.x; i < 2048; i += blockDim.x) {
        unsigned char b = m[i];
        if (b) {
            int r = i & 3;
            if (r == 1) l1 = 1;
            else if (r >= 2) l23 = 1;
        }
    }
    if (l1) atomicOr(&sflags[0], 1);
    if (l23) atomicOr(&sflags[1], 1);
    __syncthreads();
    return sflags[0] ? 0 : (sflags[1] ? 2 : 1);
}
__device__ __forceinline__ bool read_mask(const void* m, int kind, int e) {
    if (kind == 0) return ((const unsigned char*)m)[e] != 0;
    if (kind == 1) return ((const int*)m)[e] != 0;
    return ((const float*)m)[e] != 0.0f;
}

__device__ __forceinline__ void bf16_split(float f, uint16_t& hi, uint16_t& lo) {
    __nv_bfloat16 h = __float2bfloat16(f);
    float r = f - __bfloat162float(h);
    __nv_bfloat16 l = __float2bfloat16(r);
    hi = __bfloat16_as_ushort(h);
    lo = __bfloat16_as_ushort(l);
}

__device__ __forceinline__ void mma16816(float* c, const uint32_t* a,
                                         const uint32_t* b) {
    asm volatile(
        "mma.sync.aligned.m16n8k16.row.col.f32.bf16.bf16.f32 "
        "{%0,%1,%2,%3}, {%4,%5,%6,%7}, {%8,%9}, {%0,%1,%2,%3};"
        : "+f"(c[0]), "+f"(c[1]), "+f"(c[2]), "+f"(c[3])
        : "r"(a[0]), "r"(a[1]), "r"(a[2]), "r"(a[3]), "r"(b[0]), "r"(b[1]));
}

#define LDSM4(r, addr)                                                         \
    asm volatile("ldmatrix.sync.aligned.m8n8.x4.shared.b16 {%0,%1,%2,%3}, [%4];"\
        : "=r"((r)[0]), "=r"((r)[1]), "=r"((r)[2]), "=r"((r)[3]) : "r"(addr))

__device__ __forceinline__ void red_v4(float* p, float a, float b, float c,
                                       float d) {
    asm volatile("red.global.add.v4.f32 [%0], {%1,%2,%3,%4};"
                 :: "l"(p), "f"(a), "f"(b), "f"(c), "f"(d) : "memory");
}

__device__ __forceinline__ void bar_grp(int id) {
    asm volatile("bar.sync %0, 256;" :: "r"(id) : "memory");
}

// lane-split metadata: lanes 0-7 load u(row), 8-15 v(row), 16-23 mask(row)
__device__ __forceinline__ int load_lane_meta(const int* __restrict__ ei,
                                              const void* __restrict__ m,
                                              int kind, int eb, int l) {
    if (l < 8) return ei[eb + l];
    if (l < 16) return ei[NE + eb + (l - 8)];
    if (l < 24) {
        int e = eb + (l - 16);
        if (kind == 0) return ((const unsigned char*)m)[e];
        if (kind == 1) return ((const int*)m)[e];
        return (((const float*)m)[e] != 0.0f) ? 1 : 0;
    }
    return 0;
}

// ---------------------------------------------------------------------------
// Stage 1 (mma.sync): z = (EA @ W_in^T), rotate + red.v4 scatter into g_h.
// ---------------------------------------------------------------------------
__global__ void __launch_bounds__(512, 2) stage1_kernel(
    const float* __restrict__ ea, const float* __restrict__ Win,
    const int* __restrict__ ei, const void* __restrict__ mraw)
{
    extern __shared__ __align__(16) char sm1[];
    __shared__ int sflags[2];
    const int tid = threadIdx.x, w = tid >> 5, l = tid & 31;
    const int kind = detect_kind(mraw, sflags);
    const uint32_t sb = smem_u32(sm1);

    for (int x = tid; x < 64 * 64; x += 512) {
        int n = x >> 6, kp = x & 63;
        float2 wv = *(const float2*)(Win + n * IN_CH + 2 * kp);
        uint16_t h0, l0, h1, l1;
        bf16_split(wv.x, h0, l0);
        bf16_split(wv.y, h1, l1);
        uint32_t off = (uint32_t)(n * 272 + 4 * kp);
        *(uint32_t*)(sm1 + S1_W_H + off) = (uint32_t)h0 | ((uint32_t)h1 << 16);
        *(uint32_t*)(sm1 + S1_W_L + off) = (uint32_t)l0 | ((uint32_t)l1 << 16);
    }

    const int wr = w >> 2, wc = w & 3;
    const int rowb = wr * 32, colb = wc * 16;
    const int g = l >> 2, tig = l & 3;
    const uint32_t a_sub = (uint32_t)((rowb + ((l >> 3) & 1) * 8 + (l & 7)) * 272
                                      + (l >> 4) * 16);
    const uint32_t b_sub = (uint32_t)((colb + ((l >> 4) & 1) * 8 + (l & 7)) * 272
                                      + ((l >> 3) & 1) * 16);
    float* zt = (float*)(sm1 + S1_A_H);   // reused as z tile [128][68] fp32

    for (int t = blockIdx.x; t < NT; t += gridDim.x) {
        __syncthreads();   // protect A_H (z of previous tile) until scatter done
        #pragma unroll 2
        for (int rr = 0; rr < 8; rr++) {
            int r = w * 8 + rr, e = t * 128 + r;
            float4 a4 = *(const float4*)(ea + (size_t)e * IN_CH + 4 * l);
            uint16_t h0, lo0, h1, lo1, h2, lo2, h3, lo3;
            bf16_split(a4.x, h0, lo0); bf16_split(a4.y, h1, lo1);
            bf16_split(a4.z, h2, lo2); bf16_split(a4.w, h3, lo3);
            uint2 hv2, lv2;
            hv2.x = (uint32_t)h0 | ((uint32_t)h1 << 16);
            hv2.y = (uint32_t)h2 | ((uint32_t)h3 << 16);
            lv2.x = (uint32_t)lo0 | ((uint32_t)lo1 << 16);
            lv2.y = (uint32_t)lo2 | ((uint32_t)lo3 << 16);
            uint32_t off = (uint32_t)(r * 272 + 8 * l);
            *(uint2*)(sm1 + S1_A_H + off) = hv2;
            *(uint2*)(sm1 + S1_A_L + off) = lv2;
        }
        __syncthreads();

        float acc[2][2][4];
        #pragma unroll
        for (int mf = 0; mf < 2; mf++)
            #pragma unroll
            for (int nf = 0; nf < 2; nf++)
                #pragma unroll
                for (int i = 0; i < 4; i++) acc[mf][nf][i] = 0.f;

        #pragma unroll 1
        for (int pass = 0; pass < 3; pass++) {
            uint32_t Ab = sb + (pass == 1 ? S1_A_L : S1_A_H);
            uint32_t Bb = sb + (pass == 2 ? S1_W_L : S1_W_H);
            uint32_t aa0 = Ab + a_sub, aa1 = aa0 + 16 * 272;
            uint32_t ba = Bb + b_sub;
            #pragma unroll
            for (int ks = 0; ks < 8; ks++) {
                uint32_t A0[4], A1[4], B0[4];
                LDSM4(A0, aa0);
                LDSM4(A1, aa1);
                LDSM4(B0, ba);
                mma16816(acc[0][0], A0, B0);
                mma16816(acc[0][1], A0, B0 + 2);
                mma16816(acc[1][0], A1, B0);
                mma16816(acc[1][1], A1, B0 + 2);
                aa0 += 32; aa1 += 32; ba += 32;
            }
        }
        __syncthreads();   // all warps done reading A tiles -> reuse as z

        #pragma unroll
        for (int mf = 0; mf < 2; mf++) {
            int row = rowb + mf * 16 + g;
            #pragma unroll
            for (int nf = 0; nf < 2; nf++) {
                int n = colb + nf * 8 + 2 * tig;
                *(float2*)(zt + row * 68 + n) =
                    make_float2(acc[mf][nf][0], acc[mf][nf][1]);
                *(float2*)(zt + (row + 8) * 68 + n) =
                    make_float2(acc[mf][nf][2], acc[mf][nf][3]);
            }
        }
        __syncthreads();

        {
            int el = tid >> 2, q = tid & 3;
            int e = t * 128 + el;
            int u = ei[e], v = ei[NE + e];
            bool und = read_mask(mraw, kind, e);
            float cc, ss, dinv;
            if (und) { cc = 1.0f; ss = 0.0f; dinv = (u == v) ? 0.0f : RS2; }
            else     { cc = RS2;  ss = RS2;  dinv = RS2; }
            if (dinv != 0.0f) {
                const float* zr = zt + el * 68 + 16 * q;
                float* hv = g_h + (size_t)v * HID + 16 * q;
                float* hu = g_h + (size_t)u * HID + 16 * q;
                #pragma unroll
                for (int j = 0; j < 4; j++) {
                    float4 z4 = *(const float4*)(zr + 4 * j);
                    float r0 = z4.x * dinv, i0 = z4.y * dinv;
                    float r1 = z4.z * dinv, i1 = z4.w * dinv;
                    red_v4(hv + 4 * j,
                           fmaf(cc, r0, ss * i0), fmaf(cc, i0, -ss * r0),
                           fmaf(cc, r1, ss * i1), fmaf(cc, i1, -ss * r1));
                    red_v4(hu + 4 * j,
                           fmaf(-cc, r0, ss * i0), fmaf(-cc, i0, -ss * r0),
                           fmaf(-cc, r1, ss * i1), fmaf(-cc, i1, -ss * r1));
                }
            }
        }
    }
}

// ---------------------------------------------------------------------------
// Stage 2: two-tile ping-pong + tensor-phase mutex. 16 warps in two groups
// of 8; each group owns a private 64-edge tile + named barrier. A smem
// ticket (turn + done flags) serializes the MMA phases so group 0's B phase
// overlaps group 1's A/C phase and vice-versa (breaks the phase convoy that
// capped tensor util at 50%). Mutex is perf-only: groups share no writable
// smem, and done-flags make it deadlock-free under unequal tile counts.
// ---------------------------------------------------------------------------
__global__ void __launch_bounds__(512, 1) stage2_kernel(
    const float* __restrict__ ea, const float* __restrict__ Wout,
    const float* __restrict__ Wskip, const float* __restrict__ bskip,
    const float* __restrict__ bias, const int* __restrict__ ei,
    const void* __restrict__ mraw, float* __restrict__ out)
{
    extern __shared__ __align__(16) char sm[];
    __shared__ int sflags[2];
    __shared__ int s_sync[3];   // [0]=turn, [1]=done grp0, [2]=done grp1
    const int tid = threadIdx.x, l = tid & 31;
    const int kind = detect_kind(mraw, sflags);
    const uint32_t sb = smem_u32(sm);
    float* bv = (float*)(sm + S_BV);

    if (tid < 3) s_sync[tid] = 0;

    for (int x = tid; x < 128 * 32; x += 512) {         // W_out: k 0..63
        int n = x >> 5, kp = x & 31;
        float2 wv = *(const float2*)(Wout + n * HID + 2 * kp);
        uint16_t h0, l0, h1, l1;
        bf16_split(wv.x, h0, l0);
        bf16_split(wv.y, h1, l1);
        uint32_t off = (uint32_t)(n * 400 + 4 * kp);
        *(uint32_t*)(sm + W_H + off) = (uint32_t)h0 | ((uint32_t)h1 << 16);
        *(uint32_t*)(sm + W_L + off) = (uint32_t)l0 | ((uint32_t)l1 << 16);
    }
    for (int x = tid; x < 128 * 64; x += 512) {         // W_skip: k 64..191
        int n = x >> 6, kp = x & 63;
        float2 wv = *(const float2*)(Wskip + n * IN_CH + 2 * kp);
        uint16_t h0, l0, h1, l1;
        bf16_split(wv.x, h0, l0);
        bf16_split(wv.y, h1, l1);
        uint32_t off = (uint32_t)(n * 400 + 128 + 4 * kp);
        *(uint32_t*)(sm + W_H + off) = (uint32_t)h0 | ((uint32_t)h1 << 16);
        *(uint32_t*)(sm + W_L + off) = (uint32_t)l0 | ((uint32_t)l1 << 16);
    }
    if (tid < 128) bv[tid] = bskip[tid] + bias[tid];
    __syncthreads();

    const int grp = tid >> 8;            // 0 or 1
    const int gtid = tid & 255;          // thread index within group
    const int w8 = (tid >> 5) & 7;       // warp index within group
    const int barid = grp + 1;
    const uint32_t aBase = sb + (uint32_t)grp * A_GRP;

    const int wr = w8 >> 2, wc = w8 & 3; // 2x4 warp grid over 64x128 output
    const int rowb = wr * 32, colb = wc * 32;
    const int g = l >> 2, tig = l & 3;
    const uint32_t a_sub = (uint32_t)((rowb + ((l >> 3) & 1) * 8 + (l & 7)) * 400
                                      + (l >> 4) * 16);
    const uint32_t b_sub = (uint32_t)((colb + ((l >> 4) & 1) * 8 + (l & 7)) * 400
                                      + ((l >> 3) & 1) * 16);

    const int t0 = blockIdx.x * 2 + grp;
    const int tstride = gridDim.x * 2;
    int pre = 0;
    if (t0 < NT2)
        pre = load_lane_meta(ei, mraw, kind, t0 * 64 + w8 * 8, l);

    for (int t = t0; t < NT2; t += tstride) {
        // ---- Phase A: batched L2-hit gathers, stream EA, build tiles ----
        float2 phv[8], phu[8];
        #pragma unroll
        for (int r = 0; r < 8; r++) {
            int u = __shfl_sync(0xffffffffu, pre, r);
            int v = __shfl_sync(0xffffffffu, pre, r + 8);
            phv[r] = *(const float2*)(g_h + (size_t)v * HID + 2 * l);
            phu[r] = *(const float2*)(g_h + (size_t)u * HID + 2 * l);
        }
        #pragma unroll
        for (int b = 0; b < 2; b++) {
            float4 a4[4];
            #pragma unroll
            for (int rr = 0; rr < 4; rr++) {
                int e = t * 64 + w8 * 8 + b * 4 + rr;
                a4[rr] = *(const float4*)(ea + (size_t)e * IN_CH + 4 * l);
            }
            #pragma unroll
            for (int rr = 0; rr < 4; rr++) {
                int r = w8 * 8 + b * 4 + rr;
                uint16_t h0, lo0, h1, lo1, h2, lo2, h3, lo3;
                bf16_split(a4[rr].x, h0, lo0); bf16_split(a4[rr].y, h1, lo1);
                bf16_split(a4[rr].z, h2, lo2); bf16_split(a4[rr].w, h3, lo3);
                uint2 hv2, lv2;
                hv2.x = (uint32_t)h0 | ((uint32_t)h1 << 16);
                hv2.y = (uint32_t)h2 | ((uint32_t)h3 << 16);
                lv2.x = (uint32_t)lo0 | ((uint32_t)lo1 << 16);
                lv2.y = (uint32_t)lo2 | ((uint32_t)lo3 << 16);
                uint32_t off = (uint32_t)(r * 400 + 128 + 8 * l);
                *(uint2*)(sm + (aBase - sb) + off) = hv2;
                *(uint2*)(sm + (aBase - sb) + A_LOFF + off) = lv2;

                int rq = b * 4 + rr;
                int u = __shfl_sync(0xffffffffu, pre, rq);
                int v = __shfl_sync(0xffffffffu, pre, rq + 8);
                int mm = __shfl_sync(0xffffffffu, pre, rq + 16);
                float cc, ss, dinv;
                if (mm) { cc = 1.0f; ss = 0.0f; dinv = (u == v) ? 0.0f : RS2; }
                else    { cc = RS2;  ss = RS2;  dinv = RS2; }
                float av = fmaxf(phv[rq].x, 0.f), bvv = fmaxf(phv[rq].y, 0.f);
                float au = fmaxf(phu[rq].x, 0.f), bu  = fmaxf(phu[rq].y, 0.f);
                float yr = dinv * (cc * (av - au) - ss * (bvv + bu));
                float yi = dinv * (cc * (bvv - bu) + ss * (av + au));
                uint16_t yh0, yl0, yh1, yl1;
                bf16_split(yr, yh0, yl0);
                bf16_split(yi, yh1, yl1);
                uint32_t off2 = (uint32_t)(r * 400 + 4 * l);
                *(uint32_t*)(sm + (aBase - sb) + off2) =
                    (uint32_t)yh0 | ((uint32_t)yh1 << 16);
                *(uint32_t*)(sm + (aBase - sb) + A_LOFF + off2) =
                    (uint32_t)yl0 | ((uint32_t)yl1 << 16);
            }
        }
        // prefetch next tile's indices (land during Phase B)
        const int tn = t + tstride;
        pre = (tn < NT2) ? load_lane_meta(ei, mraw, kind, tn * 64 + w8 * 8, l) : 0;
        bar_grp(barid);

        // ---- acquire tensor-phase ticket (perf-only mutex) ----
        if (gtid == 0) {
            volatile int* vs = s_sync;
            while (vs[0] != grp && vs[1 + (1 - grp)] == 0) { }
        }
        bar_grp(barid);

        // ---- Phase B: fused 3-pass hi/lo mma over K=192 ----
        float acc[2][4][4];
        #pragma unroll
        for (int mf = 0; mf < 2; mf++)
            #pragma unroll
            for (int nf = 0; nf < 4; nf++)
                #pragma unroll
                for (int i = 0; i < 4; i++) acc[mf][nf][i] = 0.f;

        {
            uint32_t aH0 = aBase + a_sub, aH1 = aH0 + 16 * 400;
            uint32_t aL0 = aBase + A_LOFF + a_sub, aL1 = aL0 + 16 * 400;
            uint32_t bH0 = sb + W_H + b_sub, bH1 = bH0 + 16 * 400;
            uint32_t bL0 = sb + W_L + b_sub, bL1 = bL0 + 16 * 400;
            #pragma unroll 2
            for (int ks = 0; ks < 12; ks++) {
                uint32_t AH0[4], AH1[4], AL0[4], AL1[4];
                uint32_t BH0[4], BH1[4], BL0[4], BL1[4];
                LDSM4(AH0, aH0);
                LDSM4(AH1, aH1);
                LDSM4(BH0, bH0);
                LDSM4(BH1, bH1);
                LDSM4(AL0, aL0);
                LDSM4(AL1, aL1);
                LDSM4(BL0, bL0);
                LDSM4(BL1, bL1);
                mma16816(acc[0][0], AH0, BH0);
                mma16816(acc[0][1], AH0, BH0 + 2);
                mma16816(acc[0][2], AH0, BH1);
                mma16816(acc[0][3], AH0, BH1 + 2);
                mma16816(acc[1][0], AH1, BH0);
                mma16816(acc[1][1], AH1, BH0 + 2);
                mma16816(acc[1][2], AH1, BH1);
                mma16816(acc[1][3], AH1, BH1 + 2);
                mma16816(acc[0][0], AL0, BH0);
                mma16816(acc[0][1], AL0, BH0 + 2);
                mma16816(acc[0][2], AL0, BH1);
                mma16816(acc[0][3], AL0, BH1 + 2);
                mma16816(acc[1][0], AL1, BH0);
                mma16816(acc[1][1], AL1, BH0 + 2);
                mma16816(acc[1][2], AL1, BH1);
                mma16816(acc[1][3], AL1, BH1 + 2);
                mma16816(acc[0][0], AH0, BL0);
                mma16816(acc[0][1], AH0, BL0 + 2);
                mma16816(acc[0][2], AH0, BL1);
                mma16816(acc[0][3], AH0, BL1 + 2);
                mma16816(acc[1][0], AH1, BL0);
                mma16816(acc[1][1], AH1, BL0 + 2);
                mma16816(acc[1][2], AH1, BL1);
                mma16816(acc[1][3], AH1, BL1 + 2);
                aH0 += 32; aH1 += 32; aL0 += 32; aL1 += 32;
                bH0 += 32; bH1 += 32; bL0 += 32; bL1 += 32;
            }
        }

        // ---- release ticket: other group may start its MMA phase ----
        if (gtid == 0) ((volatile int*)s_sync)[0] = 1 - grp;

        // ---- Phase C: bias + coalesced stores ----
        #pragma unroll
        for (int mf = 0; mf < 2; mf++) {
            int e0 = t * 64 + rowb + mf * 16 + g;
            #pragma unroll
            for (int nf = 0; nf < 4; nf++) {
                int c = colb + nf * 8 + 2 * tig;
                float2 bb = *(const float2*)(bv + c);
                float2 v0, v1;
                v0.x = acc[mf][nf][0] + bb.x;
                v0.y = acc[mf][nf][1] + bb.y;
                v1.x = acc[mf][nf][2] + bb.x;
                v1.y = acc[mf][nf][3] + bb.y;
                *(float2*)(out + (size_t)e0 * OUT_CH + c) = v0;
                *(float2*)(out + (size_t)(e0 + 8) * OUT_CH + c) = v1;
            }
        }
        bar_grp(barid);   // A buffers free for next Phase A
    }

    // signal completion so the other group never waits on us again
    if (gtid == 0) ((volatile int*)s_sync)[1 + grp] = 1;
}

extern "C" void kernel_launch(void* const* d_in, const int* in_sizes, int n_in,
                              void* d_out, int out_size) {
    (void)in_sizes; (void)n_in; (void)out_size;
    const int*   ei    = (const int*)d_in[0];
    const void*  mask  = d_in[1];
    const float* ea    = (const float*)d_in[2];
    const float* Win   = (const float*)d_in[3];
    const float* Wout  = (const float*)d_in[4];
    const float* Wskip = (const float*)d_in[5];
    const float* bskip = (const float*)d_in[6];
    const float* bias  = (const float*)d_in[7];
    float* out = (float*)d_out;

    int dev = 0;
    cudaGetDevice(&dev);
    int sms = 148;
    cudaDeviceGetAttribute(&sms, cudaDevAttrMultiProcessorCount, dev);

    void* hptr = nullptr;
    cudaGetSymbolAddress(&hptr, g_h);

    cudaFuncSetAttribute(stage1_kernel,
                         cudaFuncAttributeMaxDynamicSharedMemorySize, SMEM1);
    cudaFuncSetAttribute(stage2_kernel,
                         cudaFuncAttributeMaxDynamicSharedMemorySize, SMEM2);

    cudaMemsetAsync(hptr, 0, sizeof(float) * (size_t)NN * HID);
    stage1_kernel<<<sms * 2, 512, SMEM1>>>(ea, Win, ei, mask);
    stage2_kernel<<<sms, 512, SMEM2>>>(ea, Wout, Wskip, bskip, bias, ei, mask, out);
}